// round 2
// baseline (speedup 1.0000x reference)
#include <cuda_runtime.h>
#include <cuda_bf16.h>
#include <math.h>

// Problem constants
#define BSZ   2
#define LSEQ  2048
#define HALF  1024
#define NH    16
#define HD    64
#define MTOK  (BSZ * LSEQ)            // 4096 rows
#define MH    (MTOK * HALF)           // 4,194,304 floats per (B,L,HALF) tensor
#define INV_SCALE 0.08838834764831845f   // 1/sqrt(128)

// Scratch: q_a,q_b,k_a,k_b,v_a,v_b,o_a,o_b,po_a,po_b  (10 x 16 MB)
__device__ float g_scratch[10u * MH];

// ---------------------------------------------------------------------------
// Tiled SGEMM: Y[M,N] = X[M,K] * W[N,K]^T   (torch Linear, no bias)
// 128x128 tile, BK=8, 256 threads, 8x8 per-thread microtile.
// ---------------------------------------------------------------------------
__global__ void __launch_bounds__(256) sgemm_xwt(
    const float* __restrict__ X, const float* __restrict__ W,
    float* __restrict__ Y, int M, int N, int K)
{
    __shared__ float As[8][128];
    __shared__ float Bs[8][128];

    const int bm = blockIdx.y * 128;
    const int bn = blockIdx.x * 128;
    const int tid = threadIdx.x;
    const int tx = tid & 15;       // 0..15
    const int ty = tid >> 4;       // 0..15

    const int lr = tid >> 1;        // 0..127 (tile row for loading)
    const int lc = (tid & 1) * 4;   // 0 or 4

    const float* Xp = X + (size_t)(bm + lr) * K + lc;
    const float* Wp = W + (size_t)(bn + lr) * K + lc;

    float acc[8][8];
#pragma unroll
    for (int i = 0; i < 8; i++)
#pragma unroll
        for (int j = 0; j < 8; j++) acc[i][j] = 0.f;

    for (int kt = 0; kt < K; kt += 8) {
        float4 xa = *(const float4*)(Xp + kt);
        float4 wb = *(const float4*)(Wp + kt);
        As[lc + 0][lr] = xa.x; As[lc + 1][lr] = xa.y;
        As[lc + 2][lr] = xa.z; As[lc + 3][lr] = xa.w;
        Bs[lc + 0][lr] = wb.x; Bs[lc + 1][lr] = wb.y;
        Bs[lc + 2][lr] = wb.z; Bs[lc + 3][lr] = wb.w;
        __syncthreads();

#pragma unroll
        for (int k = 0; k < 8; k++) {
            float a[8], b[8];
#pragma unroll
            for (int i = 0; i < 8; i++) a[i] = As[k][ty * 8 + i];
#pragma unroll
            for (int j = 0; j < 8; j++) b[j] = Bs[k][tx * 8 + j];
#pragma unroll
            for (int i = 0; i < 8; i++)
#pragma unroll
                for (int j = 0; j < 8; j++)
                    acc[i][j] = fmaf(a[i], b[j], acc[i][j]);
        }
        __syncthreads();
    }

#pragma unroll
    for (int i = 0; i < 8; i++) {
        float* yrow = Y + (size_t)(bm + ty * 8 + i) * N + bn + tx * 8;
#pragma unroll
        for (int j = 0; j < 8; j += 4) {
            float4 v = make_float4(acc[i][j], acc[i][j + 1], acc[i][j + 2], acc[i][j + 3]);
            *(float4*)(yrow + j) = v;
        }
    }
}

// ---------------------------------------------------------------------------
// Flash cross-attention for one direction:
//   O[b, q, h*64+d] = softmax_k( Q[b,q,h]·K[b,k,h] / SCALE ) @ V[b,k,h]
// grid (L/128, NH, B), 128 threads; thread = 1 query row.
// K/V streamed through shared 32x64 tiles.  Q pre-scaled by 1/SCALE.
// ---------------------------------------------------------------------------
__global__ void __launch_bounds__(128) flash_attn(
    const float* __restrict__ Q, const float* __restrict__ K,
    const float* __restrict__ V, float* __restrict__ O)
{
    const int qt  = blockIdx.x;
    const int h   = blockIdx.y;
    const int b   = blockIdx.z;
    const int tid = threadIdx.x;
    const int qi  = qt * 128 + tid;

    __shared__ float Ks[32][64];
    __shared__ float Vs[32][64];

    const float* qrow = Q + ((size_t)(b * LSEQ + qi)) * HALF + h * HD;
    float q[HD];
#pragma unroll
    for (int d4 = 0; d4 < 16; d4++) {
        float4 t = *(const float4*)(qrow + 4 * d4);
        q[4 * d4 + 0] = t.x * INV_SCALE;
        q[4 * d4 + 1] = t.y * INV_SCALE;
        q[4 * d4 + 2] = t.z * INV_SCALE;
        q[4 * d4 + 3] = t.w * INV_SCALE;
    }

    float o[HD];
#pragma unroll
    for (int d = 0; d < HD; d++) o[d] = 0.f;
    float m = -1e30f, l = 0.f;

    const float* Kbase = K + ((size_t)b * LSEQ) * HALF + h * HD;
    const float* Vbase = V + ((size_t)b * LSEQ) * HALF + h * HD;

    for (int kt = 0; kt < LSEQ; kt += 32) {
        __syncthreads();   // previous tile fully consumed
#pragma unroll
        for (int i = 0; i < 4; i++) {
            int idx = tid + i * 128;      // 0..511
            int r = idx >> 4, c = idx & 15;
            ((float4*)Ks[r])[c] = *(const float4*)(Kbase + (size_t)(kt + r) * HALF + 4 * c);
            ((float4*)Vs[r])[c] = *(const float4*)(Vbase + (size_t)(kt + r) * HALF + 4 * c);
        }
        __syncthreads();

        float s[32];
#pragma unroll
        for (int j = 0; j < 32; j++) {
            const float4* kr = (const float4*)Ks[j];
            float a0 = 0.f, a1 = 0.f;
#pragma unroll
            for (int d4 = 0; d4 < 16; d4 += 2) {
                float4 k0 = kr[d4];
                float4 k1 = kr[d4 + 1];
                a0 = fmaf(q[4 * d4 + 0], k0.x, a0);
                a0 = fmaf(q[4 * d4 + 1], k0.y, a0);
                a0 = fmaf(q[4 * d4 + 2], k0.z, a0);
                a0 = fmaf(q[4 * d4 + 3], k0.w, a0);
                a1 = fmaf(q[4 * d4 + 4], k1.x, a1);
                a1 = fmaf(q[4 * d4 + 5], k1.y, a1);
                a1 = fmaf(q[4 * d4 + 6], k1.z, a1);
                a1 = fmaf(q[4 * d4 + 7], k1.w, a1);
            }
            s[j] = a0 + a1;
        }

        float tm = m;
#pragma unroll
        for (int j = 0; j < 32; j++) tm = fmaxf(tm, s[j]);

        float alpha = __expf(m - tm);
        l *= alpha;
#pragma unroll
        for (int d = 0; d < HD; d++) o[d] *= alpha;

#pragma unroll
        for (int j = 0; j < 32; j++) {
            float p = __expf(s[j] - tm);
            l += p;
            const float4* vr = (const float4*)Vs[j];
#pragma unroll
            for (int d4 = 0; d4 < 16; d4++) {
                float4 vv = vr[d4];
                o[4 * d4 + 0] = fmaf(p, vv.x, o[4 * d4 + 0]);
                o[4 * d4 + 1] = fmaf(p, vv.y, o[4 * d4 + 1]);
                o[4 * d4 + 2] = fmaf(p, vv.z, o[4 * d4 + 2]);
                o[4 * d4 + 3] = fmaf(p, vv.w, o[4 * d4 + 3]);
            }
        }
        m = tm;
    }

    float inv_l = 1.f / l;
    float* orow = O + ((size_t)(b * LSEQ + qi)) * HALF + h * HD;
#pragma unroll
    for (int d4 = 0; d4 < 16; d4++) {
        float4 v = make_float4(o[4 * d4 + 0] * inv_l, o[4 * d4 + 1] * inv_l,
                               o[4 * d4 + 2] * inv_l, o[4 * d4 + 3] * inv_l);
        *(float4*)(orow + 4 * d4) = v;
    }
}

// ---------------------------------------------------------------------------
// Residual + LayerNorm:  Y = LN(X + P) * gamma + beta   (row length 1024)
// grid = MTOK rows, 256 threads (4 floats each).
// ---------------------------------------------------------------------------
__device__ __forceinline__ float warp_sum(float v) {
#pragma unroll
    for (int off = 16; off > 0; off >>= 1)
        v += __shfl_xor_sync(0xffffffffu, v, off);
    return v;
}

__global__ void __launch_bounds__(256) resid_ln(
    const float* __restrict__ X, const float* __restrict__ P,
    const float* __restrict__ gamma, const float* __restrict__ beta,
    float* __restrict__ Y)
{
    const int row = blockIdx.x;
    const int tid = threadIdx.x;
    const float* x = X + (size_t)row * HALF;
    const float* p = P + (size_t)row * HALF;

    float4 xa = *(const float4*)(x + tid * 4);
    float4 pa = *(const float4*)(p + tid * 4);
    float v0 = xa.x + pa.x, v1 = xa.y + pa.y, v2 = xa.z + pa.z, v3 = xa.w + pa.w;

    float sum = v0 + v1 + v2 + v3;
    float sq  = v0 * v0 + v1 * v1 + v2 * v2 + v3 * v3;

    __shared__ float s1[8], s2[8];
    sum = warp_sum(sum);
    sq  = warp_sum(sq);
    int wid = tid >> 5, lane = tid & 31;
    if (lane == 0) { s1[wid] = sum; s2[wid] = sq; }
    __syncthreads();
    float ts = 0.f, tq = 0.f;
#pragma unroll
    for (int i = 0; i < 8; i++) { ts += s1[i]; tq += s2[i]; }

    const float mean = ts * (1.0f / HALF);
    const float var  = tq * (1.0f / HALF) - mean * mean;
    const float inv  = rsqrtf(var + 1e-5f);

    float4 g  = *(const float4*)(gamma + tid * 4);
    float4 be = *(const float4*)(beta + tid * 4);
    float4 out;
    out.x = (v0 - mean) * inv * g.x + be.x;
    out.y = (v1 - mean) * inv * g.y + be.y;
    out.z = (v2 - mean) * inv * g.z + be.z;
    out.w = (v3 - mean) * inv * g.w + be.w;
    *(float4*)(Y + (size_t)row * HALF + tid * 4) = out;
}

// ---------------------------------------------------------------------------
// kernel_launch
// ---------------------------------------------------------------------------
extern "C" void kernel_launch(void* const* d_in, const int* in_sizes, int n_in,
                              void* d_out, int out_size)
{
    const float* x_a  = (const float*)d_in[0];
    const float* x_b  = (const float*)d_in[1];
    const float* Wq_a = (const float*)d_in[2];
    const float* Wq_b = (const float*)d_in[3];
    const float* Wk_a = (const float*)d_in[4];
    const float* Wk_b = (const float*)d_in[5];
    const float* Wv_a = (const float*)d_in[6];
    const float* Wv_b = (const float*)d_in[7];
    const float* Wo_a = (const float*)d_in[8];
    const float* Wo_b = (const float*)d_in[9];
    const float* gamma_a = (const float*)d_in[10];
    const float* beta_a  = (const float*)d_in[11];
    const float* gamma_b = (const float*)d_in[12];
    const float* beta_b  = (const float*)d_in[13];
    float* out = (float*)d_out;

    float* scr = nullptr;
    cudaGetSymbolAddress((void**)&scr, g_scratch);
    float* q_a  = scr + 0u * MH;
    float* q_b  = scr + 1u * MH;
    float* k_a  = scr + 2u * MH;
    float* k_b  = scr + 3u * MH;
    float* v_a  = scr + 4u * MH;
    float* v_b  = scr + 5u * MH;
    float* o_a  = scr + 6u * MH;
    float* o_b  = scr + 7u * MH;
    float* po_a = scr + 8u * MH;
    float* po_b = scr + 9u * MH;

    dim3 gemm_grid(HALF / 128, MTOK / 128);   // (8, 32)

    // QKV projections
    sgemm_xwt<<<gemm_grid, 256>>>(x_a, Wq_a, q_a, MTOK, HALF, HALF);
    sgemm_xwt<<<gemm_grid, 256>>>(x_b, Wq_b, q_b, MTOK, HALF, HALF);
    sgemm_xwt<<<gemm_grid, 256>>>(x_a, Wk_a, k_a, MTOK, HALF, HALF);
    sgemm_xwt<<<gemm_grid, 256>>>(x_b, Wk_b, k_b, MTOK, HALF, HALF);
    sgemm_xwt<<<gemm_grid, 256>>>(x_a, Wv_a, v_a, MTOK, HALF, HALF);
    sgemm_xwt<<<gemm_grid, 256>>>(x_b, Wv_b, v_b, MTOK, HALF, HALF);

    // Cross attention: a attends over b, b attends over a
    dim3 fa_grid(LSEQ / 128, NH, BSZ);        // (16, 16, 2)
    flash_attn<<<fa_grid, 128>>>(q_a, k_b, v_b, o_a);
    flash_attn<<<fa_grid, 128>>>(q_b, k_a, v_a, o_b);

    // Output projections
    sgemm_xwt<<<gemm_grid, 256>>>(o_a, Wo_a, po_a, MTOK, HALF, HALF);
    sgemm_xwt<<<gemm_grid, 256>>>(o_b, Wo_b, po_b, MTOK, HALF, HALF);

    // Residual + LayerNorm -> outputs (y_a then y_b, concatenated)
    resid_ln<<<MTOK, 256>>>(x_a, po_a, gamma_a, beta_a, out);
    resid_ln<<<MTOK, 256>>>(x_b, po_b, gamma_b, beta_b, out + (size_t)MH);
}